// round 5
// baseline (speedup 1.0000x reference)
#include <cuda_runtime.h>
#include <cuda_bf16.h>
#include <math.h>
#include <cstdint>

#define BATCH 4
#define SEQ   2048
#define DM    1024
#define NH    16
#define HD    64
#define QKVN  (3*DM)

// Scratch buffers (no dynamic allocation allowed)
__device__ float g_qkv[(size_t)BATCH * SEQ * QKVN];   // [B,S,3D]
__device__ float g_attn[(size_t)BATCH * SEQ * DM];    // [B,S,D]

// ===========================================================================
// Warp-level MMA helpers (base ISA: works on plain sm_103 target)
// ===========================================================================
__device__ __forceinline__ void ldsm_x4(uint32_t* r, uint32_t addr) {
    asm volatile("ldmatrix.sync.aligned.m8n8.x4.shared.b16 {%0,%1,%2,%3}, [%4];"
        : "=r"(r[0]), "=r"(r[1]), "=r"(r[2]), "=r"(r[3]) : "r"(addr));
}
__device__ __forceinline__ void ldsm_x4_t(uint32_t* r, uint32_t addr) {
    asm volatile("ldmatrix.sync.aligned.m8n8.x4.trans.shared.b16 {%0,%1,%2,%3}, [%4];"
        : "=r"(r[0]), "=r"(r[1]), "=r"(r[2]), "=r"(r[3]) : "r"(addr));
}
__device__ __forceinline__ void mma16816(float* d, const uint32_t* a, const uint32_t* b) {
    asm volatile(
        "mma.sync.aligned.m16n8k16.row.col.f32.bf16.bf16.f32 "
        "{%0,%1,%2,%3}, {%4,%5,%6,%7}, {%8,%9}, {%0,%1,%2,%3};"
        : "+f"(d[0]), "+f"(d[1]), "+f"(d[2]), "+f"(d[3])
        : "r"(a[0]), "r"(a[1]), "r"(a[2]), "r"(a[3]), "r"(b[0]), "r"(b[1]));
}

__device__ __forceinline__ uint32_t smem_to_u32(const void* smem_ptr) {
    uint32_t addr;
    asm("{ .reg .u64 tmp; cvta.to.shared.u64 tmp, %1; cvt.u32.u64 %0, tmp; }"
        : "=r"(addr) : "l"(smem_ptr));
    return addr;
}

__device__ __forceinline__ uint32_t pack_bf16_pair(float x0, float x1) {
    __nv_bfloat162 t = __floats2bfloat162_rn(x0, x1);
    return *(uint32_t*)&t;
}
__device__ __forceinline__ void split_f32(float x, float& h, float& l) {
    __nv_bfloat16 hb = __float2bfloat16_rn(x);
    h = __bfloat162float(hb);
    l = x - h;
}

// ===========================================================================
// HMMA bf16x3 GEMM: C[M,N] = A[M,K] @ B[K,N], fp32 in/out.
// CTA tile 128x128, BK=32, 256 threads (8 warps, 64x32 warp tiles in 2x4).
// ===========================================================================
#define SA 40    // As row stride (bf16 elems)
#define SB 136   // Bs row stride (bf16 elems)
#define ABUF_B (128 * SA * 2)
#define BBUF_B (32 * SB * 2)
#define BUF_B  (2 * ABUF_B + 2 * BBUF_B)
#define GEMM_SMEM_BYTES (2 * BUF_B)      // 75776

__global__ __launch_bounds__(256, 1)
void gemm_hmma3(const float* __restrict__ A, const float* __restrict__ B,
                float* __restrict__ C, int M, int N, int K)
{
    extern __shared__ char smem[];
    const uint32_t smem_u32 = smem_to_u32(smem);

    const int tid = threadIdx.x;
    const int wid = tid >> 5;
    const int lid = tid & 31;
    const int brow = blockIdx.y * 128;
    const int bcol = blockIdx.x * 128;

    const int wr = wid >> 2;     // 0..1 -> m offset wr*64
    const int wc = wid & 3;      // 0..3 -> n offset wc*32

    float acc[4][4][4];          // [mi m16][n8][quad]
#pragma unroll
    for (int i = 0; i < 4; i++)
#pragma unroll
        for (int j = 0; j < 4; j++)
#pragma unroll
            for (int q = 0; q < 4; q++) acc[i][j][q] = 0.f;

    float4 pa[4], pb[4];
    const int nkt = K >> 5;

#pragma unroll
    for (int j = 0; j < 4; j++) {
        int idx = tid * 4 + j;
        pa[j] = *(const float4*)(A + (size_t)(brow + (idx >> 3)) * K + (idx & 7) * 4);
        pb[j] = *(const float4*)(B + (size_t)(idx >> 5) * N + bcol + (idx & 31) * 4);
    }

    for (int kt = 0; kt < nkt; kt++) {
        const int sW = kt & 1;
        {
            char* base = smem + sW * BUF_B;
#pragma unroll
            for (int j = 0; j < 4; j++) {
                int idx = tid * 4 + j;
                {
                    int r = idx >> 3, c = (idx & 7) * 4;
                    float h0,l0,h1,l1,h2,l2,h3,l3;
                    split_f32(pa[j].x, h0, l0); split_f32(pa[j].y, h1, l1);
                    split_f32(pa[j].z, h2, l2); split_f32(pa[j].w, h3, l3);
                    uint32_t off = (uint32_t)(r * SA + c) * 2;
                    *(uint2*)(base + off) =
                        make_uint2(pack_bf16_pair(h0, h1), pack_bf16_pair(h2, h3));
                    *(uint2*)(base + ABUF_B + off) =
                        make_uint2(pack_bf16_pair(l0, l1), pack_bf16_pair(l2, l3));
                }
                {
                    int r = idx >> 5, c = (idx & 31) * 4;
                    float h0,l0,h1,l1,h2,l2,h3,l3;
                    split_f32(pb[j].x, h0, l0); split_f32(pb[j].y, h1, l1);
                    split_f32(pb[j].z, h2, l2); split_f32(pb[j].w, h3, l3);
                    uint32_t off = (uint32_t)(r * SB + c) * 2;
                    *(uint2*)(base + 2 * ABUF_B + off) =
                        make_uint2(pack_bf16_pair(h0, h1), pack_bf16_pair(h2, h3));
                    *(uint2*)(base + 2 * ABUF_B + BBUF_B + off) =
                        make_uint2(pack_bf16_pair(l0, l1), pack_bf16_pair(l2, l3));
                }
            }
        }
        __syncthreads();

        if (kt + 1 < nkt) {
            const int k0 = (kt + 1) << 5;
#pragma unroll
            for (int j = 0; j < 4; j++) {
                int idx = tid * 4 + j;
                pa[j] = *(const float4*)(A + (size_t)(brow + (idx >> 3)) * K + k0 + (idx & 7) * 4);
                pb[j] = *(const float4*)(B + (size_t)(k0 + (idx >> 5)) * N + bcol + (idx & 31) * 4);
            }
        }

        const uint32_t aHi = smem_u32 + sW * BUF_B;
        const uint32_t aLo = aHi + ABUF_B;
        const uint32_t bHi = aHi + 2 * ABUF_B;
        const uint32_t bLo = bHi + BBUF_B;
#pragma unroll
        for (int ks = 0; ks < 2; ks++) {
            uint32_t ahi[4][4], alo[4][4];
#pragma unroll
            for (int mi = 0; mi < 4; mi++) {
                uint32_t row = wr * 64 + mi * 16 + (lid & 15);
                uint32_t col = ks * 16 + (lid >> 4) * 8;
                uint32_t off = (row * SA + col) * 2;
                ldsm_x4(ahi[mi], aHi + off);
                ldsm_x4(alo[mi], aLo + off);
            }
            uint32_t bhi[2][4], blo[2][4];
#pragma unroll
            for (int nb = 0; nb < 2; nb++) {
                uint32_t row = ks * 16 + (lid & 15);
                uint32_t col = wc * 32 + nb * 16 + (lid >> 4) * 8;
                uint32_t off = (row * SB + col) * 2;
                ldsm_x4_t(bhi[nb], bHi + off);
                ldsm_x4_t(blo[nb], bLo + off);
            }
#pragma unroll
            for (int mi = 0; mi < 4; mi++)
#pragma unroll
                for (int nb = 0; nb < 2; nb++) {
                    float* d0 = acc[mi][nb * 2];
                    float* d1 = acc[mi][nb * 2 + 1];
                    mma16816(d0, ahi[mi], &bhi[nb][0]);
                    mma16816(d1, ahi[mi], &bhi[nb][2]);
                    mma16816(d0, ahi[mi], &blo[nb][0]);
                    mma16816(d1, ahi[mi], &blo[nb][2]);
                    mma16816(d0, alo[mi], &bhi[nb][0]);
                    mma16816(d1, alo[mi], &bhi[nb][2]);
                }
        }
        __syncthreads();
    }

    const int qrow = lid >> 2;
    const int qcol = (lid & 3) * 2;
#pragma unroll
    for (int mi = 0; mi < 4; mi++) {
        int r0 = brow + wr * 64 + mi * 16 + qrow;
#pragma unroll
        for (int nb = 0; nb < 4; nb++) {
            int c0 = bcol + wc * 32 + nb * 8 + qcol;
            float* d = acc[mi][nb];
            *(float2*)(C + (size_t)r0 * N + c0)       = make_float2(d[0], d[1]);
            *(float2*)(C + (size_t)(r0 + 8) * N + c0) = make_float2(d[2], d[3]);
        }
    }
}

// ===========================================================================
// HMMA flash attention, bf16x3 for both QK^T and PV.
// Grid: (SEQ/256, NH, BATCH). 256 threads = 8 warps; warp w owns q rows
// [w*32, w*32+32) of a 256-row q tile (two 16-row halves mi=0,1).
// Q persists in smem (hi/lo); K/V blocks of 64 keys staged per iteration.
// ===========================================================================
#define SK 72   // smem row stride in bf16 (144 B, 16B-aligned, conflict-free)
// dynamic smem layout (bytes):
#define AQHI 0
#define AQLO (256 * SK * 2)            // 36864
#define AKHI (2 * 256 * SK * 2)        // 73728
#define AKLO (AKHI + 64 * SK * 2)      // +9216
#define AVHI (AKHI + 2 * 64 * SK * 2)
#define AVLO (AKHI + 3 * 64 * SK * 2)
#define ATTN_SMEM_BYTES (AKHI + 4 * 64 * SK * 2)   // 110592

__global__ __launch_bounds__(256, 1)
void attn_hmma()
{
    extern __shared__ char dsm[];
    const uint32_t su = smem_to_u32(dsm);

    const int tid = threadIdx.x;
    const int wid = tid >> 5;
    const int lid = tid & 31;
    const int b  = blockIdx.z;
    const int h  = blockIdx.y;
    const int q0 = blockIdx.x * 256;

    const uint32_t uQhi = su + AQHI, uQlo = su + AQLO;
    const uint32_t uKhi = su + AKHI, uKlo = su + AKLO;
    const uint32_t uVhi = su + AVHI, uVlo = su + AVLO;

    // ---- stage Q (scaled by 1/8) split hi/lo: 256 rows
#pragma unroll
    for (int p = 0; p < 2; p++) {
        const int r = p * 128 + (tid >> 1);
        const int cofs = (tid & 1) * 32;
        const float* qp = g_qkv + ((size_t)(b * SEQ + q0 + r)) * QKVN + h * HD + cofs;
        char* dh = dsm + AQHI + (r * SK + cofs) * 2;
        char* dl = dsm + AQLO + (r * SK + cofs) * 2;
#pragma unroll
        for (int i = 0; i < 8; i++) {
            float4 v = *(const float4*)(qp + i * 4);
            float h0,l0,h1,l1,h2,l2,h3,l3;
            split_f32(v.x * 0.125f, h0, l0); split_f32(v.y * 0.125f, h1, l1);
            split_f32(v.z * 0.125f, h2, l2); split_f32(v.w * 0.125f, h3, l3);
            *(uint2*)(dh + i * 8) =
                make_uint2(pack_bf16_pair(h0, h1), pack_bf16_pair(h2, h3));
            *(uint2*)(dl + i * 8) =
                make_uint2(pack_bf16_pair(l0, l1), pack_bf16_pair(l2, l3));
        }
    }

    float o[2][8][4];
#pragma unroll
    for (int mi = 0; mi < 2; mi++)
#pragma unroll
        for (int j = 0; j < 8; j++)
#pragma unroll
            for (int q = 0; q < 4; q++) o[mi][j][q] = 0.f;
    float mst[2][2], lst[2][2];
#pragma unroll
    for (int mi = 0; mi < 2; mi++) {
        mst[mi][0] = -1e30f; mst[mi][1] = -1e30f;
        lst[mi][0] = 0.f;    lst[mi][1] = 0.f;
    }

    // ---- prefetch K/V block 0
    const int kr = tid >> 2;
    const int kc = (tid & 3) * 16;
    float4 pk[4], pv[4];
    {
        const float* kp = g_qkv + ((size_t)(b * SEQ + kr)) * QKVN + DM + h * HD + kc;
#pragma unroll
        for (int i = 0; i < 4; i++) {
            pk[i] = *(const float4*)(kp + i * 4);
            pv[i] = *(const float4*)(kp + DM + i * 4);
        }
    }
    __syncthreads();   // Q staged (also covers first K/V store below)

    for (int kb = 0; kb < SEQ / 64; kb++) {
        // ---- convert + store K/V block into smem
        {
            uint32_t off0 = (uint32_t)(kr * SK + kc) * 2;
#pragma unroll
            for (int i = 0; i < 4; i++) {
                float h0,l0_,h1,l1_,h2,l2_,h3,l3_;
                split_f32(pk[i].x, h0, l0_); split_f32(pk[i].y, h1, l1_);
                split_f32(pk[i].z, h2, l2_); split_f32(pk[i].w, h3, l3_);
                *(uint2*)(dsm + AKHI + off0 + i * 8) =
                    make_uint2(pack_bf16_pair(h0, h1), pack_bf16_pair(h2, h3));
                *(uint2*)(dsm + AKLO + off0 + i * 8) =
                    make_uint2(pack_bf16_pair(l0_, l1_), pack_bf16_pair(l2_, l3_));
                split_f32(pv[i].x, h0, l0_); split_f32(pv[i].y, h1, l1_);
                split_f32(pv[i].z, h2, l2_); split_f32(pv[i].w, h3, l3_);
                *(uint2*)(dsm + AVHI + off0 + i * 8) =
                    make_uint2(pack_bf16_pair(h0, h1), pack_bf16_pair(h2, h3));
                *(uint2*)(dsm + AVLO + off0 + i * 8) =
                    make_uint2(pack_bf16_pair(l0_, l1_), pack_bf16_pair(l2_, l3_));
            }
        }
        __syncthreads();

        // ---- prefetch next block
        if (kb + 1 < SEQ / 64) {
            const float* kp = g_qkv +
                ((size_t)(b * SEQ + (kb + 1) * 64 + kr)) * QKVN + DM + h * HD + kc;
#pragma unroll
            for (int i = 0; i < 4; i++) {
                pk[i] = *(const float4*)(kp + i * 4);
                pv[i] = *(const float4*)(kp + DM + i * 4);
            }
        }

        // ---- S = Q K^T  (32 x 64 per warp), bf16x3; K frags shared across mi
        float s[2][8][4];
#pragma unroll
        for (int mi = 0; mi < 2; mi++)
#pragma unroll
            for (int j = 0; j < 8; j++)
#pragma unroll
                for (int q = 0; q < 4; q++) s[mi][j][q] = 0.f;

#pragma unroll
        for (int t = 0; t < 4; t++) {
            uint32_t qh[2][4], ql[2][4];
#pragma unroll
            for (int mi = 0; mi < 2; mi++) {
                uint32_t row = wid * 32 + mi * 16 + (lid & 15);
                uint32_t off = (row * SK + t * 16 + (lid >> 4) * 8) * 2;
                ldsm_x4(qh[mi], uQhi + off);
                ldsm_x4(ql[mi], uQlo + off);
            }
#pragma unroll
            for (int j2 = 0; j2 < 4; j2++) {
                uint32_t kh[4], kl[4];
                uint32_t off = ((j2 * 16 + (lid & 7) + ((lid >> 4) & 1) * 8) * SK
                                + t * 16 + ((lid >> 3) & 1) * 8) * 2;
                ldsm_x4(kh, uKhi + off);
                ldsm_x4(kl, uKlo + off);
#pragma unroll
                for (int mi = 0; mi < 2; mi++) {
                    float* d0 = s[mi][j2 * 2];
                    float* d1 = s[mi][j2 * 2 + 1];
                    mma16816(d0, qh[mi], &kh[0]); mma16816(d1, qh[mi], &kh[2]);
                    mma16816(d0, qh[mi], &kl[0]); mma16816(d1, qh[mi], &kl[2]);
                    mma16816(d0, ql[mi], &kh[0]); mma16816(d1, ql[mi], &kh[2]);
                }
            }
        }

        // ---- online softmax + pack P (per mi)
        uint32_t phi[2][4][4], plo[2][4][4];
#pragma unroll
        for (int mi = 0; mi < 2; mi++) {
            float mx0 = s[mi][0][0], mx1 = s[mi][0][2];
#pragma unroll
            for (int j = 0; j < 8; j++) {
                mx0 = fmaxf(mx0, fmaxf(s[mi][j][0], s[mi][j][1]));
                mx1 = fmaxf(mx1, fmaxf(s[mi][j][2], s[mi][j][3]));
            }
            mx0 = fmaxf(mx0, __shfl_xor_sync(0xffffffff, mx0, 1));
            mx0 = fmaxf(mx0, __shfl_xor_sync(0xffffffff, mx0, 2));
            mx1 = fmaxf(mx1, __shfl_xor_sync(0xffffffff, mx1, 1));
            mx1 = fmaxf(mx1, __shfl_xor_sync(0xffffffff, mx1, 2));

            const float mn0 = fmaxf(mst[mi][0], mx0);
            const float mn1 = fmaxf(mst[mi][1], mx1);
            const float c0 = __expf(mst[mi][0] - mn0);
            const float c1 = __expf(mst[mi][1] - mn1);
            mst[mi][0] = mn0; mst[mi][1] = mn1;

            float rl0 = 0.f, rl1 = 0.f;
#pragma unroll
            for (int j = 0; j < 8; j++) {
                s[mi][j][0] = __expf(s[mi][j][0] - mn0); rl0 += s[mi][j][0];
                s[mi][j][1] = __expf(s[mi][j][1] - mn0); rl0 += s[mi][j][1];
                s[mi][j][2] = __expf(s[mi][j][2] - mn1); rl1 += s[mi][j][2];
                s[mi][j][3] = __expf(s[mi][j][3] - mn1); rl1 += s[mi][j][3];
            }
            rl0 += __shfl_xor_sync(0xffffffff, rl0, 1);
            rl0 += __shfl_xor_sync(0xffffffff, rl0, 2);
            rl1 += __shfl_xor_sync(0xffffffff, rl1, 1);
            rl1 += __shfl_xor_sync(0xffffffff, rl1, 2);
            lst[mi][0] = lst[mi][0] * c0 + rl0;
            lst[mi][1] = lst[mi][1] * c1 + rl1;

#pragma unroll
            for (int j = 0; j < 8; j++) {
                o[mi][j][0] *= c0; o[mi][j][1] *= c0;
                o[mi][j][2] *= c1; o[mi][j][3] *= c1;
            }

#pragma unroll
            for (int t = 0; t < 4; t++) {
                const int j = 2 * t;
                float h0,lo0,h1,lo1;
                split_f32(s[mi][j][0], h0, lo0);   split_f32(s[mi][j][1], h1, lo1);
                phi[mi][t][0] = pack_bf16_pair(h0, h1);  plo[mi][t][0] = pack_bf16_pair(lo0, lo1);
                split_f32(s[mi][j][2], h0, lo0);   split_f32(s[mi][j][3], h1, lo1);
                phi[mi][t][1] = pack_bf16_pair(h0, h1);  plo[mi][t][1] = pack_bf16_pair(lo0, lo1);
                split_f32(s[mi][j+1][0], h0, lo0); split_f32(s[mi][j+1][1], h1, lo1);
                phi[mi][t][2] = pack_bf16_pair(h0, h1);  plo[mi][t][2] = pack_bf16_pair(lo0, lo1);
                split_f32(s[mi][j+1][2], h0, lo0); split_f32(s[mi][j+1][3], h1, lo1);
                phi[mi][t][3] = pack_bf16_pair(h0, h1);  plo[mi][t][3] = pack_bf16_pair(lo0, lo1);
            }
        }

        // ---- O += P V  (bf16x3); V frags shared across mi
#pragma unroll
        for (int t = 0; t < 4; t++) {
#pragma unroll
            for (int j2 = 0; j2 < 4; j2++) {
                uint32_t vh[4], vl[4];
                uint32_t off = ((t * 16 + (lid & 15)) * SK
                                + j2 * 16 + (lid >> 4) * 8) * 2;
                ldsm_x4_t(vh, uVhi + off);
                ldsm_x4_t(vl, uVlo + off);
#pragma unroll
                for (int mi = 0; mi < 2; mi++) {
                    float* d0 = o[mi][j2 * 2];
                    float* d1 = o[mi][j2 * 2 + 1];
                    mma16816(d0, phi[mi][t], &vh[0]); mma16816(d1, phi[mi][t], &vh[2]);
                    mma16816(d0, phi[mi][t], &vl[0]); mma16816(d1, phi[mi][t], &vl[2]);
                    mma16816(d0, plo[mi][t], &vh[0]); mma16816(d1, plo[mi][t], &vh[2]);
                }
            }
        }
        __syncthreads();
    }

    // ---- epilogue
#pragma unroll
    for (int mi = 0; mi < 2; mi++) {
        const float inv0 = 1.f / lst[mi][0];
        const float inv1 = 1.f / lst[mi][1];
        const int gr0 = q0 + wid * 32 + mi * 16 + (lid >> 2);
        const int col = h * HD + (lid & 3) * 2;
#pragma unroll
        for (int j = 0; j < 8; j++) {
            float* p0 = g_attn + ((size_t)(b * SEQ + gr0)) * DM + col + j * 8;
            float* p1 = g_attn + ((size_t)(b * SEQ + gr0 + 8)) * DM + col + j * 8;
            *(float2*)p0 = make_float2(o[mi][j][0] * inv0, o[mi][j][1] * inv0);
            *(float2*)p1 = make_float2(o[mi][j][2] * inv1, o[mi][j][3] * inv1);
        }
    }
}

// ---------------------------------------------------------------------------
extern "C" void kernel_launch(void* const* d_in, const int* in_sizes, int n_in,
                              void* d_out, int out_size)
{
    const float* x     = (const float*)d_in[0];   // [4,2048,1024]
    const float* w_qkv = (const float*)d_in[1];   // [1024,3072]
    const float* w_out = (const float*)d_in[2];   // [1024,1024]
    float* out = (float*)d_out;                   // [4,2048,1024]

    float* qkv_ptr;
    float* attn_ptr;
    cudaGetSymbolAddress((void**)&qkv_ptr,  g_qkv);
    cudaGetSymbolAddress((void**)&attn_ptr, g_attn);

    cudaFuncSetAttribute(gemm_hmma3,
                         cudaFuncAttributeMaxDynamicSharedMemorySize,
                         GEMM_SMEM_BYTES);
    cudaFuncSetAttribute(attn_hmma,
                         cudaFuncAttributeMaxDynamicSharedMemorySize,
                         ATTN_SMEM_BYTES);

    const int M = BATCH * SEQ;  // 8192

    // 1) QKV projection: [8192,1024] @ [1024,3072]
    {
        dim3 grid(QKVN / 128, M / 128);
        gemm_hmma3<<<grid, 256, GEMM_SMEM_BYTES>>>(x, w_qkv, qkv_ptr, M, QKVN, DM);
    }

    // 2) Attention (HMMA flash)
    {
        dim3 grid(SEQ / 256, NH, BATCH);
        attn_hmma<<<grid, 256, ATTN_SMEM_BYTES>>>();
    }

    // 3) Output projection: [8192,1024] @ [1024,1024]
    {
        dim3 grid(DM / 128, M / 128);
        gemm_hmma3<<<grid, 256, GEMM_SMEM_BYTES>>>(attn_ptr, w_out, out, M, DM, DM);
    }
}

// round 6
// speedup vs baseline: 1.0977x; 1.0977x over previous
#include <cuda_runtime.h>
#include <cuda_bf16.h>
#include <math.h>
#include <cstdint>

#define BATCH 4
#define SEQ   2048
#define DM    1024
#define NH    16
#define HD    64
#define QKVN  (3*DM)

// Scratch buffers (no dynamic allocation allowed)
__device__ float g_qkv[(size_t)BATCH * SEQ * QKVN];   // [B,S,3D]
__device__ float g_attn[(size_t)BATCH * SEQ * DM];    // [B,S,D]

// ===========================================================================
// Warp-level MMA helpers (base ISA: works on plain sm_103 target)
// ===========================================================================
__device__ __forceinline__ void ldsm_x4(uint32_t* r, uint32_t addr) {
    asm volatile("ldmatrix.sync.aligned.m8n8.x4.shared.b16 {%0,%1,%2,%3}, [%4];"
        : "=r"(r[0]), "=r"(r[1]), "=r"(r[2]), "=r"(r[3]) : "r"(addr));
}
__device__ __forceinline__ void ldsm_x4_t(uint32_t* r, uint32_t addr) {
    asm volatile("ldmatrix.sync.aligned.m8n8.x4.trans.shared.b16 {%0,%1,%2,%3}, [%4];"
        : "=r"(r[0]), "=r"(r[1]), "=r"(r[2]), "=r"(r[3]) : "r"(addr));
}
__device__ __forceinline__ void mma16816(float* d, const uint32_t* a, const uint32_t* b) {
    asm volatile(
        "mma.sync.aligned.m16n8k16.row.col.f32.bf16.bf16.f32 "
        "{%0,%1,%2,%3}, {%4,%5,%6,%7}, {%8,%9}, {%0,%1,%2,%3};"
        : "+f"(d[0]), "+f"(d[1]), "+f"(d[2]), "+f"(d[3])
        : "r"(a[0]), "r"(a[1]), "r"(a[2]), "r"(a[3]), "r"(b[0]), "r"(b[1]));
}

__device__ __forceinline__ uint32_t smem_to_u32(const void* smem_ptr) {
    uint32_t addr;
    asm("{ .reg .u64 tmp; cvta.to.shared.u64 tmp, %1; cvt.u32.u64 %0, tmp; }"
        : "=r"(addr) : "l"(smem_ptr));
    return addr;
}

__device__ __forceinline__ float ex2f(float x) {
    float y;
    asm("ex2.approx.f32 %0, %1;" : "=f"(y) : "f"(x));
    return y;
}

__device__ __forceinline__ uint32_t pack_bf16_pair(float x0, float x1) {
    __nv_bfloat162 t = __floats2bfloat162_rn(x0, x1);
    return *(uint32_t*)&t;
}
__device__ __forceinline__ void split_f32(float x, float& h, float& l) {
    __nv_bfloat16 hb = __float2bfloat16_rn(x);
    h = __bfloat162float(hb);
    l = x - h;
}

// ===========================================================================
// HMMA bf16x3 GEMM: C[M,N] = A[M,K] @ B[K,N], fp32 in/out.
// CTA tile 128x128, BK=32, 256 threads (8 warps, 32x64 warp tiles).
// Single barrier per k-tile (store | BAR | MMA with 2 buffers).
// ===========================================================================
#define SA 40    // As row stride (bf16 elems)
#define SB 136   // Bs row stride (bf16 elems)
#define ABUF_B (128 * SA * 2)
#define BBUF_B (32 * SB * 2)
#define BUF_B  (2 * ABUF_B + 2 * BBUF_B)
#define GEMM_SMEM_BYTES (2 * BUF_B)      // 75776

__global__ __launch_bounds__(256, 1)
void gemm_hmma3(const float* __restrict__ A, const float* __restrict__ B,
                float* __restrict__ C, int M, int N, int K)
{
    extern __shared__ char smem[];
    const uint32_t smem_u32 = smem_to_u32(smem);

    const int tid = threadIdx.x;
    const int wid = tid >> 5;
    const int lid = tid & 31;
    const int brow = blockIdx.y * 128;
    const int bcol = blockIdx.x * 128;

    const int wr = wid >> 1;     // 0..3 -> m offset wr*32
    const int wc = wid & 1;      // 0..1 -> n offset wc*64

    float acc[2][8][4];
#pragma unroll
    for (int i = 0; i < 2; i++)
#pragma unroll
        for (int j = 0; j < 8; j++)
#pragma unroll
            for (int q = 0; q < 4; q++) acc[i][j][q] = 0.f;

    float4 pa[4], pb[4];
    const int nkt = K >> 5;

#pragma unroll
    for (int j = 0; j < 4; j++) {
        int idx = tid * 4 + j;
        pa[j] = *(const float4*)(A + (size_t)(brow + (idx >> 3)) * K + (idx & 7) * 4);
        pb[j] = *(const float4*)(B + (size_t)(idx >> 5) * N + bcol + (idx & 31) * 4);
    }

    for (int kt = 0; kt < nkt; kt++) {
        const int sW = kt & 1;
        {
            char* base = smem + sW * BUF_B;
#pragma unroll
            for (int j = 0; j < 4; j++) {
                int idx = tid * 4 + j;
                {
                    int r = idx >> 3, c = (idx & 7) * 4;
                    float h0,l0,h1,l1,h2,l2,h3,l3;
                    split_f32(pa[j].x, h0, l0); split_f32(pa[j].y, h1, l1);
                    split_f32(pa[j].z, h2, l2); split_f32(pa[j].w, h3, l3);
                    uint32_t off = (uint32_t)(r * SA + c) * 2;
                    *(uint2*)(base + off) =
                        make_uint2(pack_bf16_pair(h0, h1), pack_bf16_pair(h2, h3));
                    *(uint2*)(base + ABUF_B + off) =
                        make_uint2(pack_bf16_pair(l0, l1), pack_bf16_pair(l2, l3));
                }
                {
                    int r = idx >> 5, c = (idx & 31) * 4;
                    float h0,l0,h1,l1,h2,l2,h3,l3;
                    split_f32(pb[j].x, h0, l0); split_f32(pb[j].y, h1, l1);
                    split_f32(pb[j].z, h2, l2); split_f32(pb[j].w, h3, l3);
                    uint32_t off = (uint32_t)(r * SB + c) * 2;
                    *(uint2*)(base + 2 * ABUF_B + off) =
                        make_uint2(pack_bf16_pair(h0, h1), pack_bf16_pair(h2, h3));
                    *(uint2*)(base + 2 * ABUF_B + BBUF_B + off) =
                        make_uint2(pack_bf16_pair(l0, l1), pack_bf16_pair(l2, l3));
                }
            }
        }
        __syncthreads();   // store(kt) done; MMA(kt) below overlaps store(kt+1) of
                           // faster warps, which targets the other buffer.

        if (kt + 1 < nkt) {
            const int k0 = (kt + 1) << 5;
#pragma unroll
            for (int j = 0; j < 4; j++) {
                int idx = tid * 4 + j;
                pa[j] = *(const float4*)(A + (size_t)(brow + (idx >> 3)) * K + k0 + (idx & 7) * 4);
                pb[j] = *(const float4*)(B + (size_t)(k0 + (idx >> 5)) * N + bcol + (idx & 31) * 4);
            }
        }

        const uint32_t aHi = smem_u32 + sW * BUF_B;
        const uint32_t aLo = aHi + ABUF_B;
        const uint32_t bHi = aHi + 2 * ABUF_B;
        const uint32_t bLo = bHi + BBUF_B;
#pragma unroll
        for (int ks = 0; ks < 2; ks++) {
            uint32_t ahi[2][4], alo[2][4];
#pragma unroll
            for (int mi = 0; mi < 2; mi++) {
                uint32_t row = wr * 32 + mi * 16 + (lid & 15);
                uint32_t col = ks * 16 + (lid >> 4) * 8;
                uint32_t off = (row * SA + col) * 2;
                ldsm_x4(ahi[mi], aHi + off);
                ldsm_x4(alo[mi], aLo + off);
            }
            uint32_t bhi[4][4], blo[4][4];
#pragma unroll
            for (int nb = 0; nb < 4; nb++) {
                uint32_t row = ks * 16 + (lid & 15);
                uint32_t col = wc * 64 + nb * 16 + (lid >> 4) * 8;
                uint32_t off = (row * SB + col) * 2;
                ldsm_x4_t(bhi[nb], bHi + off);
                ldsm_x4_t(blo[nb], bLo + off);
            }
            // pass-reordered: all hi*hi, then hi*lo, then lo*hi (dep distance 16)
#pragma unroll
            for (int pass = 0; pass < 3; pass++) {
#pragma unroll
                for (int mi = 0; mi < 2; mi++)
#pragma unroll
                    for (int nb = 0; nb < 4; nb++) {
                        const uint32_t* af = (pass == 2) ? alo[mi] : ahi[mi];
                        const uint32_t* bf = (pass == 1) ? blo[nb] : bhi[nb];
                        mma16816(acc[mi][nb * 2],     af, &bf[0]);
                        mma16816(acc[mi][nb * 2 + 1], af, &bf[2]);
                    }
            }
        }
    }

    const int qrow = lid >> 2;
    const int qcol = (lid & 3) * 2;
#pragma unroll
    for (int mi = 0; mi < 2; mi++) {
        int r0 = brow + wr * 32 + mi * 16 + qrow;
#pragma unroll
        for (int nb = 0; nb < 8; nb++) {
            int c0 = bcol + wc * 64 + nb * 8 + qcol;
            float* d = acc[mi][nb];
            *(float2*)(C + (size_t)r0 * N + c0)       = make_float2(d[0], d[1]);
            *(float2*)(C + (size_t)(r0 + 8) * N + c0) = make_float2(d[2], d[3]);
        }
    }
}

// ===========================================================================
// HMMA flash attention, bf16x3 for both QK^T and PV.
// Grid: (SEQ/256, NH, BATCH). 256 threads = 8 warps; warp w owns q rows
// [w*32, w*32+32) (two 16-row halves). Q persists in smem (hi/lo);
// K/V double-buffered in smem, one barrier per 64-key block. exp2 softmax.
// ===========================================================================
#define SK 72   // smem row stride in bf16 (144 B, 16B-aligned, conflict-free)
// dynamic smem layout (bytes):
#define AQHI 0
#define AQLO (256 * SK * 2)            // 36864
#define AKV  (2 * 256 * SK * 2)        // 73728
#define KVST (4 * 64 * SK * 2)         // 36864 per stage
#define OKHI 0
#define OKLO (64 * SK * 2)             // +9216
#define OVHI (2 * 64 * SK * 2)
#define OVLO (3 * 64 * SK * 2)
#define ATTN_SMEM_BYTES (AKV + 2 * KVST)   // 147456

__global__ __launch_bounds__(256, 1)
void attn_hmma()
{
    extern __shared__ char dsm[];
    const uint32_t su = smem_to_u32(dsm);

    const int tid = threadIdx.x;
    const int wid = tid >> 5;
    const int lid = tid & 31;
    const int b  = blockIdx.z;
    const int h  = blockIdx.y;
    const int q0 = blockIdx.x * 256;

    const uint32_t uQhi = su + AQHI, uQlo = su + AQLO;

    const float QSCALE = 0.125f * 1.4426950408889634f;   // (1/sqrt(64)) * log2(e)

    // ---- stage Q (scaled) split hi/lo: 256 rows
#pragma unroll
    for (int p = 0; p < 2; p++) {
        const int r = p * 128 + (tid >> 1);
        const int cofs = (tid & 1) * 32;
        const float* qp = g_qkv + ((size_t)(b * SEQ + q0 + r)) * QKVN + h * HD + cofs;
        char* dh = dsm + AQHI + (r * SK + cofs) * 2;
        char* dl = dsm + AQLO + (r * SK + cofs) * 2;
#pragma unroll
        for (int i = 0; i < 8; i++) {
            float4 v = *(const float4*)(qp + i * 4);
            float h0,l0,h1,l1,h2,l2,h3,l3;
            split_f32(v.x * QSCALE, h0, l0); split_f32(v.y * QSCALE, h1, l1);
            split_f32(v.z * QSCALE, h2, l2); split_f32(v.w * QSCALE, h3, l3);
            *(uint2*)(dh + i * 8) =
                make_uint2(pack_bf16_pair(h0, h1), pack_bf16_pair(h2, h3));
            *(uint2*)(dl + i * 8) =
                make_uint2(pack_bf16_pair(l0, l1), pack_bf16_pair(l2, l3));
        }
    }

    float o[2][8][4];
#pragma unroll
    for (int mi = 0; mi < 2; mi++)
#pragma unroll
        for (int j = 0; j < 8; j++)
#pragma unroll
            for (int q = 0; q < 4; q++) o[mi][j][q] = 0.f;
    float mst[2][2], lst[2][2];
#pragma unroll
    for (int mi = 0; mi < 2; mi++) {
        mst[mi][0] = -1e30f; mst[mi][1] = -1e30f;
        lst[mi][0] = 0.f;    lst[mi][1] = 0.f;
    }

    // ---- prefetch K/V block 0
    const int kr = tid >> 2;
    const int kc = (tid & 3) * 16;
    float4 pk[4], pv[4];
    {
        const float* kp = g_qkv + ((size_t)(b * SEQ + kr)) * QKVN + DM + h * HD + kc;
#pragma unroll
        for (int i = 0; i < 4; i++) {
            pk[i] = *(const float4*)(kp + i * 4);
            pv[i] = *(const float4*)(kp + DM + i * 4);
        }
    }

    for (int kb = 0; kb < SEQ / 64; kb++) {
        const uint32_t stB = AKV + (uint32_t)(kb & 1) * KVST;
        // ---- convert + store K/V block into smem stage kb%2
        {
            char* sb = dsm + stB;
            uint32_t off0 = (uint32_t)(kr * SK + kc) * 2;
#pragma unroll
            for (int i = 0; i < 4; i++) {
                float h0,l0_,h1,l1_,h2,l2_,h3,l3_;
                split_f32(pk[i].x, h0, l0_); split_f32(pk[i].y, h1, l1_);
                split_f32(pk[i].z, h2, l2_); split_f32(pk[i].w, h3, l3_);
                *(uint2*)(sb + OKHI + off0 + i * 8) =
                    make_uint2(pack_bf16_pair(h0, h1), pack_bf16_pair(h2, h3));
                *(uint2*)(sb + OKLO + off0 + i * 8) =
                    make_uint2(pack_bf16_pair(l0_, l1_), pack_bf16_pair(l2_, l3_));
                split_f32(pv[i].x, h0, l0_); split_f32(pv[i].y, h1, l1_);
                split_f32(pv[i].z, h2, l2_); split_f32(pv[i].w, h3, l3_);
                *(uint2*)(sb + OVHI + off0 + i * 8) =
                    make_uint2(pack_bf16_pair(h0, h1), pack_bf16_pair(h2, h3));
                *(uint2*)(sb + OVLO + off0 + i * 8) =
                    make_uint2(pack_bf16_pair(l0_, l1_), pack_bf16_pair(l2_, l3_));
            }
        }
        __syncthreads();   // single barrier: MMAs below overlap faster warps'
                           // stores of block kb+1 into the other stage.

        // ---- prefetch next block
        if (kb + 1 < SEQ / 64) {
            const float* kp = g_qkv +
                ((size_t)(b * SEQ + (kb + 1) * 64 + kr)) * QKVN + DM + h * HD + kc;
#pragma unroll
            for (int i = 0; i < 4; i++) {
                pk[i] = *(const float4*)(kp + i * 4);
                pv[i] = *(const float4*)(kp + DM + i * 4);
            }
        }

        const uint32_t uKhi = su + stB + OKHI, uKlo = su + stB + OKLO;
        const uint32_t uVhi = su + stB + OVHI, uVlo = su + stB + OVLO;

        // ---- S = Q K^T  (32 x 64 per warp), bf16x3; K frags shared across mi
        float s[2][8][4];
#pragma unroll
        for (int mi = 0; mi < 2; mi++)
#pragma unroll
            for (int j = 0; j < 8; j++)
#pragma unroll
                for (int q = 0; q < 4; q++) s[mi][j][q] = 0.f;

#pragma unroll
        for (int t = 0; t < 4; t++) {
            uint32_t qh[2][4], ql[2][4];
#pragma unroll
            for (int mi = 0; mi < 2; mi++) {
                uint32_t row = wid * 32 + mi * 16 + (lid & 15);
                uint32_t off = (row * SK + t * 16 + (lid >> 4) * 8) * 2;
                ldsm_x4(qh[mi], uQhi + off);
                ldsm_x4(ql[mi], uQlo + off);
            }
#pragma unroll
            for (int j2 = 0; j2 < 4; j2++) {
                uint32_t kh[4], kl[4];
                uint32_t off = ((j2 * 16 + (lid & 7) + ((lid >> 4) & 1) * 8) * SK
                                + t * 16 + ((lid >> 3) & 1) * 8) * 2;
                ldsm_x4(kh, uKhi + off);
                ldsm_x4(kl, uKlo + off);
#pragma unroll
                for (int mi = 0; mi < 2; mi++) {
                    float* d0 = s[mi][j2 * 2];
                    float* d1 = s[mi][j2 * 2 + 1];
                    mma16816(d0, qh[mi], &kh[0]); mma16816(d1, qh[mi], &kh[2]);
                    mma16816(d0, qh[mi], &kl[0]); mma16816(d1, qh[mi], &kl[2]);
                    mma16816(d0, ql[mi], &kh[0]); mma16816(d1, ql[mi], &kh[2]);
                }
            }
        }

        // ---- online softmax (log2 domain) + pack P (per mi)
        uint32_t phi[2][4][4], plo[2][4][4];
#pragma unroll
        for (int mi = 0; mi < 2; mi++) {
            float mx0 = s[mi][0][0], mx1 = s[mi][0][2];
#pragma unroll
            for (int j = 0; j < 8; j++) {
                mx0 = fmaxf(mx0, fmaxf(s[mi][j][0], s[mi][j][1]));
                mx1 = fmaxf(mx1, fmaxf(s[mi][j][2], s[mi][j][3]));
            }
            mx0 = fmaxf(mx0, __shfl_xor_sync(0xffffffff, mx0, 1));
            mx0 = fmaxf(mx0, __shfl_xor_sync(0xffffffff, mx0, 2));
            mx1 = fmaxf(mx1, __shfl_xor_sync(0xffffffff, mx1, 1));
            mx1 = fmaxf(mx1, __shfl_xor_sync(0xffffffff, mx1, 2));

            const float mn0 = fmaxf(mst[mi][0], mx0);
            const float mn1 = fmaxf(mst[mi][1], mx1);
            const float c0 = ex2f(mst[mi][0] - mn0);
            const float c1 = ex2f(mst[mi][1] - mn1);
            mst[mi][0] = mn0; mst[mi][1] = mn1;

            float rl0 = 0.f, rl1 = 0.f;
#pragma unroll
            for (int j = 0; j < 8; j++) {
                s[mi][j][0] = ex2f(s[mi][j][0] - mn0); rl0 += s[mi][j][0];
                s[mi][j][1] = ex2f(s[mi][j][1] - mn0); rl0 += s[mi][j][1];
                s[mi][j][2] = ex2f(s[mi][j][2] - mn1); rl1 += s[mi][j][2];
                s[mi][j][3] = ex2f(s[mi][j][3] - mn1); rl1 += s[mi][j][3];
            }
            rl0 += __shfl_xor_sync(0xffffffff, rl0, 1);
            rl0 += __shfl_xor_sync(0xffffffff, rl0, 2);
            rl1 += __shfl_xor_sync(0xffffffff, rl1, 1);
            rl1 += __shfl_xor_sync(0xffffffff, rl1, 2);
            lst[mi][0] = lst[mi][0] * c0 + rl0;
            lst[mi][1] = lst[mi][1] * c1 + rl1;

#pragma unroll
            for (int j = 0; j < 8; j++) {
                o[mi][j][0] *= c0; o[mi][j][1] *= c0;
                o[mi][j][2] *= c1; o[mi][j][3] *= c1;
            }

#pragma unroll
            for (int t = 0; t < 4; t++) {
                const int j = 2 * t;
                float h0,lo0,h1,lo1;
                split_f32(s[mi][j][0], h0, lo0);   split_f32(s[mi][j][1], h1, lo1);
                phi[mi][t][0] = pack_bf16_pair(h0, h1);  plo[mi][t][0] = pack_bf16_pair(lo0, lo1);
                split_f32(s[mi][j][2], h0, lo0);   split_f32(s[mi][j][3], h1, lo1);
                phi[mi][t][1] = pack_bf16_pair(h0, h1);  plo[mi][t][1] = pack_bf16_pair(lo0, lo1);
                split_f32(s[mi][j+1][0], h0, lo0); split_f32(s[mi][j+1][1], h1, lo1);
                phi[mi][t][2] = pack_bf16_pair(h0, h1);  plo[mi][t][2] = pack_bf16_pair(lo0, lo1);
                split_f32(s[mi][j+1][2], h0, lo0); split_f32(s[mi][j+1][3], h1, lo1);
                phi[mi][t][3] = pack_bf16_pair(h0, h1);  plo[mi][t][3] = pack_bf16_pair(lo0, lo1);
            }
        }

        // ---- O += P V  (bf16x3); V frags shared across mi
#pragma unroll
        for (int t = 0; t < 4; t++) {
#pragma unroll
            for (int j2 = 0; j2 < 4; j2++) {
                uint32_t vh[4], vl[4];
                uint32_t off = ((t * 16 + (lid & 15)) * SK
                                + j2 * 16 + (lid >> 4) * 8) * 2;
                ldsm_x4_t(vh, uVhi + off);
                ldsm_x4_t(vl, uVlo + off);
#pragma unroll
                for (int mi = 0; mi < 2; mi++) {
                    float* d0 = o[mi][j2 * 2];
                    float* d1 = o[mi][j2 * 2 + 1];
                    mma16816(d0, phi[mi][t], &vh[0]); mma16816(d1, phi[mi][t], &vh[2]);
                    mma16816(d0, phi[mi][t], &vl[0]); mma16816(d1, phi[mi][t], &vl[2]);
                    mma16816(d0, plo[mi][t], &vh[0]); mma16816(d1, plo[mi][t], &vh[2]);
                }
            }
        }
        // no trailing barrier: next iteration writes the other KV stage
    }

    // ---- epilogue
#pragma unroll
    for (int mi = 0; mi < 2; mi++) {
        const float inv0 = 1.f / lst[mi][0];
        const float inv1 = 1.f / lst[mi][1];
        const int gr0 = q0 + wid * 32 + mi * 16 + (lid >> 2);
        const int col = h * HD + (lid & 3) * 2;
#pragma unroll
        for (int j = 0; j < 8; j++) {
            float* p0 = g_attn + ((size_t)(b * SEQ + gr0)) * DM + col + j * 8;
            float* p1 = g_attn + ((size_t)(b * SEQ + gr0 + 8)) * DM + col + j * 8;
            *(float2*)p0 = make_float2(o[mi][j][0] * inv0, o[mi][j][1] * inv0);
            *(float2*)p1 = make_float2(o[mi][j][2] * inv1, o[mi][j][3] * inv1);
        }
    }
}

// ---------------------------------------------------------------------------
extern "C" void kernel_launch(void* const* d_in, const int* in_sizes, int n_in,
                              void* d_out, int out_size)
{
    const float* x     = (const float*)d_in[0];   // [4,2048,1024]
    const float* w_qkv = (const float*)d_in[1];   // [1024,3072]
    const float* w_out = (const float*)d_in[2];   // [1024,1024]
    float* out = (float*)d_out;                   // [4,2048,1024]

    float* qkv_ptr;
    float* attn_ptr;
    cudaGetSymbolAddress((void**)&qkv_ptr,  g_qkv);
    cudaGetSymbolAddress((void**)&attn_ptr, g_attn);

    cudaFuncSetAttribute(gemm_hmma3,
                         cudaFuncAttributeMaxDynamicSharedMemorySize,
                         GEMM_SMEM_BYTES);
    cudaFuncSetAttribute(attn_hmma,
                         cudaFuncAttributeMaxDynamicSharedMemorySize,
                         ATTN_SMEM_BYTES);

    const int M = BATCH * SEQ;  // 8192

    // 1) QKV projection: [8192,1024] @ [1024,3072]
    {
        dim3 grid(QKVN / 128, M / 128);
        gemm_hmma3<<<grid, 256, GEMM_SMEM_BYTES>>>(x, w_qkv, qkv_ptr, M, QKVN, DM);
    }

    // 2) Attention (HMMA flash)
    {
        dim3 grid(SEQ / 256, NH, BATCH);
        attn_hmma<<<grid, 256, ATTN_SMEM_BYTES>>>();
    }

    // 3) Output projection: [8192,1024] @ [1024,1024]
    {
        dim3 grid(DM / 128, M / 128);
        gemm_hmma3<<<grid, 256, GEMM_SMEM_BYTES>>>(attn_ptr, w_out, out, M, DM, DM);
    }
}